// round 16
// baseline (speedup 1.0000x reference)
#include <cuda_runtime.h>
#include <math.h>

#define KGRID 64
#define NRAY2 4096
#define NS    64
#define OUTN  192
#define OUT3  (OUTN*OUTN*OUTN)

#define FUSED_BLOCKS 148
#define RAY_WARPS_PER_BLOCK 7          // 1036 slots, 1024 used (4 rays/warp, 8 lanes/ray)
#define BUILD_WARPS_PER_BLOCK 9
#define N_TILES      (OUTN * 6 * 6)    // 6912
#define N_BUILD_WARPS (FUSED_BLOCKS * BUILD_WARPS_PER_BLOCK)   // 1332

// ---------------- scratch ----------------
__device__ float4 gM4[NRAY2 * NS];   // mesh {2X-1, 2Y-1, 2z-1, _}
// z-FASTEST transposed volume (plain float, 28MB):
//   gVolT[(y*192 + x)*192 + z] = vol[z][y][x]
__device__ float gVolT[OUT3];

// ---------------- compile-time matrices ----------------
constexpr double c_sin(double x) {
    double x2 = x * x;
    return x * (1.0 + x2 * (-1.0/6.0 + x2 * (1.0/120.0 + x2 * (-1.0/5040.0
             + x2 * (1.0/362880.0 + x2 * (-1.0/39916800.0))))));
}
constexpr double c_cos(double x) {
    double x2 = x * x;
    return 1.0 + x2 * (-0.5 + x2 * (1.0/24.0 + x2 * (-1.0/720.0
             + x2 * (1.0/40320.0 + x2 * (-1.0/3628800.0 + x2 * (1.0/479001600.0))))));
}
struct M4m { double a[16]; };
constexpr M4m c_mul(const M4m& A, const M4m& B) {
    M4m C{};
    for (int i = 0; i < 4; i++)
        for (int j = 0; j < 4; j++) {
            double s = 0.0;
            for (int k = 0; k < 4; k++) s += A.a[i*4+k] * B.a[k*4+j];
            C.a[i*4+j] = s;
        }
    return C;
}
constexpr M4m c_ry(double t) { double c=c_cos(t), s=c_sin(t); return M4m{{1,0,0,0, 0,c,-s,0, 0,s,c,0, 0,0,0,1}}; }
constexpr M4m c_rx(double t) { double c=c_cos(t), s=c_sin(t); return M4m{{c,0,-s,0, 0,1,0,0, s,0,c,0, 0,0,0,1}}; }
constexpr M4m c_rz(double t) { double c=c_cos(t), s=c_sin(t); return M4m{{c,-s,0,0, s,c,0,0, 0,0,1,0, 0,0,0,1}}; }
struct Mats { float mc[12]; float md[12]; };
constexpr Mats build_mats() {
    const double TX = 0.1, TY = 0.05, TZ = 0.02, CX = 0.5;
    M4m RY  = c_ry(-TY), RY_ = c_ry( TY);
    M4m RX  = c_rx( TX), RX_ = c_rx(-TX);
    M4m RZ  = c_rz(-TZ), RZ_ = c_rz( TZ);
    M4m S1{{1,0,0,0, 0,1,0,0, 0,0,1,0, -CX,-CX,-CX,1}};
    M4m S2{{1,0,0,0, 0,1,0,0, 0,0,1,0,  CX, CX, CX,1}};
    M4m M_crd = c_mul(c_mul(c_mul(c_mul(S1, RZ), RY), RX), S2);
    M4m M_drv = c_mul(c_mul(RX_, RY_), RZ_);
    Mats r{};
    for (int i = 0; i < 4; i++)
        for (int j = 0; j < 3; j++) {
            r.mc[i*3+j] = (float)M_crd.a[i*4+j];
            r.md[i*3+j] = (float)M_drv.a[i*4+j];
        }
    return r;
}
__constant__ Mats cMat = build_mats();

// ---------------- dummy kernel: shifts ncu -s 5 capture onto ray_build ----------------
__global__ void noop_kernel() {}

// ---------------- ray-tracing body (R6/R13 structure, proven) ----------------
__device__ __forceinline__ void ray_body(const float* __restrict__ RI,
                                         const float* __restrict__ ray0,
                                         int warp_global, int lane) {
    int grp  = (lane >> 3);
    int l    = lane & 7;
    int ray  = warp_global * 4 + grp;
    if (ray >= NRAY2) return;

    float mc[12], md[12];
#pragma unroll
    for (int i = 0; i < 12; i++) { mc[i] = cMat.mc[i]; md[i] = cMat.md[i]; }

    const float* r0 = ray0 + ray * 5;
    float X = r0[0], dX1 = r0[1], Y = r0[2], dY1 = r0[3], z = r0[4];

    float xr[4], yr[4], zr[4];
    bool  act[4];
#pragma unroll
    for (int k = 0; k < 4; k++) {
        int m = l + 8 * k;
        act[k] = (m < 27);
        int mm = act[k] ? m : 0;
        xr[k] = (float)((mm / 3) % 3 - 1);
        yr[k] = (float)(mm / 9 - 1);
        zr[k] = (float)(mm % 3 - 1);
    }

    const float2* ri2 = (const float2*)RI;
    const float STEP  = 1.0f / 63.0f;
    const float INV63 = 1.0f / 63.0f;

    if (l == 0)
        gM4[ray * NS] = make_float4(2.0f*X - 1.0f, 2.0f*Y - 1.0f, 2.0f*z - 1.0f, 0.0f);

    float cXv, cYv, cZv;
    float cfX[4], cfY[4], cfZ[4];
    float2 ri_cur[4];
    {
        float t0 = Y * mc[0] + X * mc[3] + z * mc[6] + mc[9];
        float t1 = Y * mc[1] + X * mc[4] + z * mc[7] + mc[10];
        float t2 = Y * mc[2] + X * mc[5] + z * mc[8] + mc[11];
        cXv = t1; cYv = t0; cZv = t2;
        float rX = rintf(cXv * 64.0f), rY = rintf(cYv * 64.0f), rZ = rintf(cZv * 64.0f);
#pragma unroll
        for (int k = 0; k < 4; k++) {
            cfX[k] = fminf(fmaxf(rX + xr[k], 0.0f), 63.0f);
            cfY[k] = fminf(fmaxf(rY + yr[k], 0.0f), 63.0f);
            cfZ[k] = fminf(fmaxf(rZ + zr[k], 0.0f), 63.0f);
            ri_cur[k] = make_float2(0.f, 1.f);
            if (act[k]) {
                int lin = ((int)cfY[k] << 12) + ((int)cfX[k] << 6) + (int)cfZ[k];
                ri_cur[k] = __ldg(&ri2[lin]);
            }
        }
    }

    for (int s = 1; s < NS; s++) {
        float Xn = X + dX1 * STEP;
        float Yn = Y + dY1 * STEP;
        float zn = z + STEP;

        float t0 = Yn * mc[0] + Xn * mc[3] + zn * mc[6] + mc[9];
        float t1 = Yn * mc[1] + Xn * mc[4] + zn * mc[7] + mc[10];
        float t2 = Yn * mc[2] + Xn * mc[5] + zn * mc[8] + mc[11];
        float nXv = t1, nYv = t0, nZv = t2;
        float rX = rintf(nXv * 64.0f), rY = rintf(nYv * 64.0f), rZ = rintf(nZv * 64.0f);
        float nfX[4], nfY[4], nfZ[4];
        float2 ri_next[4];
#pragma unroll
        for (int k = 0; k < 4; k++) {
            nfX[k] = fminf(fmaxf(rX + xr[k], 0.0f), 63.0f);
            nfY[k] = fminf(fmaxf(rY + yr[k], 0.0f), 63.0f);
            nfZ[k] = fminf(fmaxf(rZ + zr[k], 0.0f), 63.0f);
            ri_next[k] = make_float2(0.f, 1.f);
            if (act[k]) {
                int lin = ((int)nfY[k] << 12) + ((int)nfX[k] << 6) + (int)nfZ[k];
                ri_next[k] = __ldg(&ri2[lin]);
            }
        }

        float s_norm = 0.f, s_nus = 0.f, s_nx = 0.f, s_ny = 0.f,
              s_nz = 0.f, s_ndx = 0.f, s_ndy = 0.f, s_ndz = 0.f;
#pragma unroll
        for (int k = 0; k < 4; k++) {
            if (act[k]) {
                float dx  = cfX[k] * INV63 - cXv;
                float dy  = cfY[k] * INV63 - cYv;
                float dzv = cfZ[k] * INV63 - cZv;
                float A = ri_cur[k].x, sg = ri_cur[k].y;
                float inv_s2 = __fdividef(1.0f, sg * sg);
                float r2 = dx * dx + dy * dy + dzv * dzv;
                float ni = __expf(-r2 * 0.5f * inv_s2) + 2e-7f;
                float nu = ni * A;
                float hx = dx * inv_s2, hy = dy * inv_s2, hz = dzv * inv_s2;
                s_norm += ni;      s_nus += nu;
                s_nx += nu * hx;   s_ny += nu * hy;   s_nz += nu * hz;
                s_ndx += ni * hx;  s_ndy += ni * hy;  s_ndz += ni * hz;
            }
        }
#pragma unroll
        for (int off = 4; off > 0; off >>= 1) {
            s_norm += __shfl_xor_sync(0xffffffffu, s_norm, off);
            s_nus  += __shfl_xor_sync(0xffffffffu, s_nus,  off);
            s_nx   += __shfl_xor_sync(0xffffffffu, s_nx,   off);
            s_ny   += __shfl_xor_sync(0xffffffffu, s_ny,   off);
            s_nz   += __shfl_xor_sync(0xffffffffu, s_nz,   off);
            s_ndx  += __shfl_xor_sync(0xffffffffu, s_ndx,  off);
            s_ndy  += __shfl_xor_sync(0xffffffffu, s_ndy,  off);
            s_ndz  += __shfl_xor_sync(0xffffffffu, s_ndz,  off);
        }
        float inv_norm = __fdividef(1.0f, s_norm);
        float inv_n2 = inv_norm * inv_norm;
        float nx = (s_norm * s_nx - s_nus * s_ndx) * inv_n2;
        float ny = (s_norm * s_ny - s_nus * s_ndy) * inv_n2;
        float nz = (s_norm * s_nz - s_nus * s_ndz) * inv_n2;

        float d0 = ny * md[0] + nx * md[3] + nz * md[6] + md[9];
        float d1 = ny * md[1] + nx * md[4] + nz * md[7] + md[10];
        float d2 = ny * md[2] + nx * md[5] + nz * md[8] + md[11];
        float dndx = d1, dndz = d2, dndy = d0;

        float inv_n = __fdividef(s_norm, s_nus);
        float dX2 = (dndx - dndz * dX1) * (1.0f + dX1 * dX1) * inv_n;
        float dY2 = (dndy - dndz * dY1) * (1.0f + dY1 * dY1) * inv_n;

        dX1 += dX2 * STEP;
        dY1 += dY2 * STEP;
        X = Xn; Y = Yn; z = zn;

        if (l == 0)
            gM4[ray * NS + s] = make_float4(2.0f*X - 1.0f, 2.0f*Y - 1.0f, 2.0f*z - 1.0f, 0.0f);

        cXv = nXv; cYv = nYv; cZv = nZv;
#pragma unroll
        for (int k = 0; k < 4; k++) {
            cfX[k] = nfX[k]; cfY[k] = nfY[k]; cfZ[k] = nfZ[k];
            ri_cur[k] = ri_next[k];
        }
    }
}

// ---------------- per-warp transpose tile: (y, 32x, 32z) -> scalar gVolT ----------------
// Phase B uses float4 z-quad stores: 8 STG.128 per lane instead of 32 STG.32.
// LDS pattern smA[zq+j][xi] is conflict-free: word (4k*33 + x) mod 32 = 4k+x,
// distinct across lanes.
__device__ __forceinline__ void build_tile(float (*smA)[33],
                                           const float* __restrict__ vol,
                                           int tile, int lane) {
    int y    = tile / 36;
    int rest = tile % 36;
    int x0   = (rest / 6) * 32;
    int z0   = (rest % 6) * 32;

#pragma unroll 4
    for (int zi = 0; zi < 32; zi++) {
        const float* rowp = &vol[((z0 + zi) * OUTN + y) * OUTN];
        smA[zi][lane] = __ldg(rowp + x0 + lane);
    }
    __syncwarp();

    int zq = (lane & 7) * 4;       // z-quad start: 0,4,...,28
    int xg = lane >> 3;            // 0..3
#pragma unroll
    for (int it = 0; it < 8; it++) {
        int xi = xg + it * 4;      // covers 0..31
        float4 v = make_float4(smA[zq + 0][xi], smA[zq + 1][xi],
                               smA[zq + 2][xi], smA[zq + 3][xi]);
        *(float4*)&gVolT[((y * OUTN) + x0 + xi) * OUTN + z0 + zq] = v;
    }
    __syncwarp();
}

// ---------------- fused kernel: warps 0-6 rays, warps 7-15 build ----------------
__global__ void __launch_bounds__(512) ray_build_kernel(const float* __restrict__ RI,
                                                        const float* __restrict__ ray0,
                                                        const float* __restrict__ vol) {
    __shared__ float smA[BUILD_WARPS_PER_BLOCK][32][33];   // 38KB

    int wid  = threadIdx.x >> 5;
    int lane = threadIdx.x & 31;

    if (wid < RAY_WARPS_PER_BLOCK) {
        int warp_global = blockIdx.x * RAY_WARPS_PER_BLOCK + wid;
        if (warp_global < NRAY2 / 4)
            ray_body(RI, ray0, warp_global, lane);
    } else {
        int bw = blockIdx.x * BUILD_WARPS_PER_BLOCK + (wid - RAY_WARPS_PER_BLOCK);
        for (int tile = bw; tile < N_TILES; tile += N_BUILD_WARPS)
            build_tile(smA[wid - RAY_WARPS_PER_BLOCK], vol, tile, lane);
    }
}

// ---------------- phase 2: lane t handles cc = q*32+t -> contiguous z addresses ----------------
__device__ __forceinline__ float tap_slow(int x, int y, int z) {
    bool in = ((unsigned)x < 192u) && ((unsigned)y < 192u) && ((unsigned)z < 192u);
    int xc = min(max(x, 0), 191);
    int yc = min(max(y, 0), 191);
    int zc = min(max(z, 0), 191);
    float v = __ldg(&gVolT[((yc * OUTN) + xc) * OUTN + zc]);
    return in ? v : 0.0f;
}

__global__ void __launch_bounds__(256) sample_kernel(float* __restrict__ out) {
    int w = threadIdx.x >> 5;
    int t = threadIdx.x & 31;
    int row = blockIdx.x * 8 + w;
    int aa = row / OUTN, bb = row % OUTN;

    __shared__ float4 G4[8][64];

    const float scale = 63.0f / 191.0f;
    float pa = (float)aa * scale; int i0 = min((int)pa, 62); float wi = pa - (float)i0;
    float pb = (float)bb * scale; int j0 = min((int)pb, 62); float wj = pb - (float)j0;
    float u = 1.0f - wi, v = 1.0f - wj;
    int base = (i0 << 12) + (j0 << 6);

#pragma unroll
    for (int sb = 0; sb < 2; sb++) {
        int s = t + sb * 32;
        float4 a00 = gM4[base + s],      a10 = gM4[base + 4096 + s];
        float4 a01 = gM4[base + 64 + s], a11 = gM4[base + 4160 + s];
        float4 g;
        g.x = (a00.x * u + a10.x * wi) * v + (a01.x * u + a11.x * wi) * wj;
        g.y = (a00.y * u + a10.y * wi) * v + (a01.y * u + a11.y * wi) * wj;
        g.z = (a00.z * u + a10.z * wi) * v + (a01.z * u + a11.z * wi) * wj;
        g.w = 0.0f;
        G4[w][s] = g;
    }
    __syncwarp();

    int obase = row * OUTN;
#pragma unroll
    for (int q = 0; q < 6; q++) {
        int cc = q * 32 + t;
        float pc = (float)cc * scale; int s0 = min((int)pc, 62); float ws = pc - (float)s0;
        float4 g0 = G4[w][s0];
        float4 g1 = G4[w][s0 + 1];
        float gx = g0.x * (1.0f - ws) + g1.x * ws;
        float gy = g0.y * (1.0f - ws) + g1.y * ws;
        float gz = g0.z * (1.0f - ws) + g1.z * ws;

        float ix = (gx + 1.0f) * 0.5f * 191.0f;
        float iy = (gy + 1.0f) * 0.5f * 191.0f;
        float iz = (gz + 1.0f) * 0.5f * 191.0f;
        float xf = floorf(ix), yf = floorf(iy), zf = floorf(iz);
        float fx = ix - xf, fy = iy - yf, fz = iz - zf;
        int x0 = (int)xf, y0 = (int)yf, z0 = (int)zf;

        float v000, v001, v100, v101, v010, v011, v110, v111;
        bool lane_ok = ((unsigned)x0 <= 190u) && ((unsigned)y0 <= 190u) &&
                       ((unsigned)z0 <= 190u);
        if (__all_sync(0xffffffffu, lane_ok)) {
            const float* p = &gVolT[((y0 * OUTN) + x0) * OUTN + z0];
            v000 = __ldg(p);                  v001 = __ldg(p + 1);
            v100 = __ldg(p + OUTN);           v101 = __ldg(p + OUTN + 1);
            v010 = __ldg(p + OUTN*OUTN);      v011 = __ldg(p + OUTN*OUTN + 1);
            v110 = __ldg(p + OUTN*OUTN+OUTN); v111 = __ldg(p + OUTN*OUTN+OUTN + 1);
        } else {
            v000 = tap_slow(x0,     y0,     z0);
            v001 = tap_slow(x0,     y0,     z0 + 1);
            v100 = tap_slow(x0 + 1, y0,     z0);
            v101 = tap_slow(x0 + 1, y0,     z0 + 1);
            v010 = tap_slow(x0,     y0 + 1, z0);
            v011 = tap_slow(x0,     y0 + 1, z0 + 1);
            v110 = tap_slow(x0 + 1, y0 + 1, z0);
            v111 = tap_slow(x0 + 1, y0 + 1, z0 + 1);
        }

        float ux = 1.0f - fx, uy = 1.0f - fy;
        float r0 = uy * (ux * v000 + fx * v100) + fy * (ux * v010 + fx * v110);
        float r1 = uy * (ux * v001 + fx * v101) + fy * (ux * v011 + fx * v111);
        out[obase + cc] = r0 * (1.0f - fz) + r1 * fz;
    }
}

// ---------------- launch ----------------
// Launch pattern [noop, ray_build, sample, noop]: period-4 launch stream puts
// ncu's fixed "-s 5 -c 1" capture (index 5 mod 4 == 1) on ray_build.
extern "C" void kernel_launch(void* const* d_in, const int* in_sizes, int n_in,
                              void* d_out, int out_size) {
    const float* phantom = nullptr;
    const float* RI      = nullptr;
    const float* ray0    = nullptr;
    for (int i = 0; i < n_in; i++) {
        if      (in_sizes[i] == OUT3)                phantom = (const float*)d_in[i];
        else if (in_sizes[i] == KGRID*KGRID*KGRID*2) RI      = (const float*)d_in[i];
        else if (in_sizes[i] == NRAY2 * 5)           ray0    = (const float*)d_in[i];
    }
    float* out = (float*)d_out;

    noop_kernel<<<1, 32>>>();
    ray_build_kernel<<<FUSED_BLOCKS, 512>>>(RI, ray0, phantom);
    sample_kernel<<<OUTN * OUTN / 8, 256>>>(out);
    noop_kernel<<<1, 32>>>();
}

// round 17
// speedup vs baseline: 1.0917x; 1.0917x over previous
#include <cuda_runtime.h>
#include <math.h>

#define KGRID 64
#define NRAY2 4096
#define NS    64
#define OUTN  192
#define OUT3  (OUTN*OUTN*OUTN)

#define FUSED_BLOCKS 148
#define RAY_WARPS_PER_BLOCK 7          // 1036 slots, 1024 used (4 rays/warp, 8 lanes/ray)
#define BUILD_WARPS_PER_BLOCK 9
#define N_TILES      (OUTN * 6 * 6)    // 6912
#define N_BUILD_WARPS (FUSED_BLOCKS * BUILD_WARPS_PER_BLOCK)   // 1332

// ---------------- scratch ----------------
__device__ float4 gM4[NRAY2 * NS];   // mesh {2X-1, 2Y-1, 2z-1, _}
// z-FASTEST transposed volume: gVolT[(y*192 + x)*192 + z] = vol[z][y][x]
__device__ float gVolT[OUT3];

// ---------------- compile-time matrices ----------------
constexpr double c_sin(double x) {
    double x2 = x * x;
    return x * (1.0 + x2 * (-1.0/6.0 + x2 * (1.0/120.0 + x2 * (-1.0/5040.0
             + x2 * (1.0/362880.0 + x2 * (-1.0/39916800.0))))));
}
constexpr double c_cos(double x) {
    double x2 = x * x;
    return 1.0 + x2 * (-0.5 + x2 * (1.0/24.0 + x2 * (-1.0/720.0
             + x2 * (1.0/40320.0 + x2 * (-1.0/3628800.0 + x2 * (1.0/479001600.0))))));
}
struct M4m { double a[16]; };
constexpr M4m c_mul(const M4m& A, const M4m& B) {
    M4m C{};
    for (int i = 0; i < 4; i++)
        for (int j = 0; j < 4; j++) {
            double s = 0.0;
            for (int k = 0; k < 4; k++) s += A.a[i*4+k] * B.a[k*4+j];
            C.a[i*4+j] = s;
        }
    return C;
}
constexpr M4m c_ry(double t) { double c=c_cos(t), s=c_sin(t); return M4m{{1,0,0,0, 0,c,-s,0, 0,s,c,0, 0,0,0,1}}; }
constexpr M4m c_rx(double t) { double c=c_cos(t), s=c_sin(t); return M4m{{c,0,-s,0, 0,1,0,0, s,0,c,0, 0,0,0,1}}; }
constexpr M4m c_rz(double t) { double c=c_cos(t), s=c_sin(t); return M4m{{c,-s,0,0, s,c,0,0, 0,0,1,0, 0,0,0,1}}; }
struct Mats { float mc[12]; float md[12]; };
constexpr Mats build_mats() {
    const double TX = 0.1, TY = 0.05, TZ = 0.02, CX = 0.5;
    M4m RY  = c_ry(-TY), RY_ = c_ry( TY);
    M4m RX  = c_rx( TX), RX_ = c_rx(-TX);
    M4m RZ  = c_rz(-TZ), RZ_ = c_rz( TZ);
    M4m S1{{1,0,0,0, 0,1,0,0, 0,0,1,0, -CX,-CX,-CX,1}};
    M4m S2{{1,0,0,0, 0,1,0,0, 0,0,1,0,  CX, CX, CX,1}};
    M4m M_crd = c_mul(c_mul(c_mul(c_mul(S1, RZ), RY), RX), S2);
    M4m M_drv = c_mul(c_mul(RX_, RY_), RZ_);
    Mats r{};
    for (int i = 0; i < 4; i++)
        for (int j = 0; j < 3; j++) {
            r.mc[i*3+j] = (float)M_crd.a[i*4+j];
            r.md[i*3+j] = (float)M_drv.a[i*4+j];
        }
    return r;
}
__constant__ Mats cMat = build_mats();

// ---------------- ray-tracing body (R6 structure + interior fast path) ----------------
__device__ __forceinline__ void ray_body(const float* __restrict__ RI,
                                         const float* __restrict__ ray0,
                                         int warp_global, int lane) {
    int grp  = (lane >> 3);
    int l    = lane & 7;
    int ray  = warp_global * 4 + grp;
    if (ray >= NRAY2) return;

    float mc[12], md[12];
#pragma unroll
    for (int i = 0; i < 12; i++) { mc[i] = cMat.mc[i]; md[i] = cMat.md[i]; }

    const float* r0 = ray0 + ray * 5;
    float X = r0[0], dX1 = r0[1], Y = r0[2], dY1 = r0[3], z = r0[4];

    float xr[4], yr[4], zr[4];
    int   doff[4];
    bool  act[4];
#pragma unroll
    for (int k = 0; k < 4; k++) {
        int m = l + 8 * k;
        act[k] = (m < 27);
        int mm = act[k] ? m : 0;
        int xi = (mm / 3) % 3 - 1;
        int yi = mm / 9 - 1;
        int zi = mm % 3 - 1;
        xr[k] = (float)xi;  yr[k] = (float)yi;  zr[k] = (float)zi;
        doff[k] = (yi << 12) + (xi << 6) + zi;
    }

    const float2* ri2 = (const float2*)RI;
    const float STEP  = 1.0f / 63.0f;
    const float INV63 = 1.0f / 63.0f;

    if (l == 0)
        gM4[ray * NS] = make_float4(2.0f*X - 1.0f, 2.0f*Y - 1.0f, 2.0f*z - 1.0f, 0.0f);

    float cXv, cYv, cZv;
    float cfX[4], cfY[4], cfZ[4];
    float2 ri_cur[4];
    {
        float t0 = Y * mc[0] + X * mc[3] + z * mc[6] + mc[9];
        float t1 = Y * mc[1] + X * mc[4] + z * mc[7] + mc[10];
        float t2 = Y * mc[2] + X * mc[5] + z * mc[8] + mc[11];
        cXv = t1; cYv = t0; cZv = t2;
        float rX = rintf(cXv * 64.0f), rY = rintf(cYv * 64.0f), rZ = rintf(cZv * 64.0f);
#pragma unroll
        for (int k = 0; k < 4; k++) {
            cfX[k] = fminf(fmaxf(rX + xr[k], 0.0f), 63.0f);
            cfY[k] = fminf(fmaxf(rY + yr[k], 0.0f), 63.0f);
            cfZ[k] = fminf(fmaxf(rZ + zr[k], 0.0f), 63.0f);
            ri_cur[k] = make_float2(0.f, 1.f);
            if (act[k]) {
                int lin = ((int)cfY[k] << 12) + ((int)cfX[k] << 6) + (int)cfZ[k];
                ri_cur[k] = __ldg(&ri2[lin]);
            }
        }
    }

    for (int s = 1; s < NS; s++) {
        float Xn = X + dX1 * STEP;
        float Yn = Y + dY1 * STEP;
        float zn = z + STEP;

        float t0 = Yn * mc[0] + Xn * mc[3] + zn * mc[6] + mc[9];
        float t1 = Yn * mc[1] + Xn * mc[4] + zn * mc[7] + mc[10];
        float t2 = Yn * mc[2] + Xn * mc[5] + zn * mc[8] + mc[11];
        float nXv = t1, nYv = t0, nZv = t2;
        float rX = rintf(nXv * 64.0f), rY = rintf(nYv * 64.0f), rZ = rintf(nZv * 64.0f);
        float nfX[4], nfY[4], nfZ[4];
        float2 ri_next[4];

        // interior fast path: base in [1,62]^3 -> no clamps, lin = base + doff[k]
        bool ok = (rX >= 1.0f) && (rX <= 62.0f) &&
                  (rY >= 1.0f) && (rY <= 62.0f) &&
                  (rZ >= 1.0f) && (rZ <= 62.0f);
        if (__all_sync(0xffffffffu, ok)) {
            int base = ((int)rY << 12) + ((int)rX << 6) + (int)rZ;
#pragma unroll
            for (int k = 0; k < 4; k++) {
                nfX[k] = rX + xr[k];
                nfY[k] = rY + yr[k];
                nfZ[k] = rZ + zr[k];
                ri_next[k] = make_float2(0.f, 1.f);
                if (act[k]) ri_next[k] = __ldg(&ri2[base + doff[k]]);
            }
        } else {
#pragma unroll
            for (int k = 0; k < 4; k++) {
                nfX[k] = fminf(fmaxf(rX + xr[k], 0.0f), 63.0f);
                nfY[k] = fminf(fmaxf(rY + yr[k], 0.0f), 63.0f);
                nfZ[k] = fminf(fmaxf(rZ + zr[k], 0.0f), 63.0f);
                ri_next[k] = make_float2(0.f, 1.f);
                if (act[k]) {
                    int lin = ((int)nfY[k] << 12) + ((int)nfX[k] << 6) + (int)nfZ[k];
                    ri_next[k] = __ldg(&ri2[lin]);
                }
            }
        }

        float s_norm = 0.f, s_nus = 0.f, s_nx = 0.f, s_ny = 0.f,
              s_nz = 0.f, s_ndx = 0.f, s_ndy = 0.f, s_ndz = 0.f;
#pragma unroll
        for (int k = 0; k < 4; k++) {
            if (act[k]) {
                float dx  = cfX[k] * INV63 - cXv;
                float dy  = cfY[k] * INV63 - cYv;
                float dzv = cfZ[k] * INV63 - cZv;
                float A = ri_cur[k].x, sg = ri_cur[k].y;
                float inv_s2 = __fdividef(1.0f, sg * sg);
                float r2 = dx * dx + dy * dy + dzv * dzv;
                float ni = __expf(-r2 * 0.5f * inv_s2) + 2e-7f;
                float nu = ni * A;
                float hx = dx * inv_s2, hy = dy * inv_s2, hz = dzv * inv_s2;
                s_norm += ni;      s_nus += nu;
                s_nx += nu * hx;   s_ny += nu * hy;   s_nz += nu * hz;
                s_ndx += ni * hx;  s_ndy += ni * hy;  s_ndz += ni * hz;
            }
        }
#pragma unroll
        for (int off = 4; off > 0; off >>= 1) {
            s_norm += __shfl_xor_sync(0xffffffffu, s_norm, off);
            s_nus  += __shfl_xor_sync(0xffffffffu, s_nus,  off);
            s_nx   += __shfl_xor_sync(0xffffffffu, s_nx,   off);
            s_ny   += __shfl_xor_sync(0xffffffffu, s_ny,   off);
            s_nz   += __shfl_xor_sync(0xffffffffu, s_nz,   off);
            s_ndx  += __shfl_xor_sync(0xffffffffu, s_ndx,  off);
            s_ndy  += __shfl_xor_sync(0xffffffffu, s_ndy,  off);
            s_ndz  += __shfl_xor_sync(0xffffffffu, s_ndz,  off);
        }
        float inv_norm = __fdividef(1.0f, s_norm);
        float inv_n2 = inv_norm * inv_norm;
        float nx = (s_norm * s_nx - s_nus * s_ndx) * inv_n2;
        float ny = (s_norm * s_ny - s_nus * s_ndy) * inv_n2;
        float nz = (s_norm * s_nz - s_nus * s_ndz) * inv_n2;

        float d0 = ny * md[0] + nx * md[3] + nz * md[6] + md[9];
        float d1 = ny * md[1] + nx * md[4] + nz * md[7] + md[10];
        float d2 = ny * md[2] + nx * md[5] + nz * md[8] + md[11];
        float dndx = d1, dndz = d2, dndy = d0;

        float inv_n = __fdividef(s_norm, s_nus);
        float dX2 = (dndx - dndz * dX1) * (1.0f + dX1 * dX1) * inv_n;
        float dY2 = (dndy - dndz * dY1) * (1.0f + dY1 * dY1) * inv_n;

        dX1 += dX2 * STEP;
        dY1 += dY2 * STEP;
        X = Xn; Y = Yn; z = zn;

        if (l == 0)
            gM4[ray * NS + s] = make_float4(2.0f*X - 1.0f, 2.0f*Y - 1.0f, 2.0f*z - 1.0f, 0.0f);

        cXv = nXv; cYv = nYv; cZv = nZv;
#pragma unroll
        for (int k = 0; k < 4; k++) {
            cfX[k] = nfX[k]; cfY[k] = nfY[k]; cfZ[k] = nfZ[k];
            ri_cur[k] = ri_next[k];
        }
    }
}

// ---------------- per-warp transpose tile: (y, 32x, 32z) -> scalar gVolT ----------------
__device__ __forceinline__ void build_tile(float (*smA)[33],
                                           const float* __restrict__ vol,
                                           int tile, int lane) {
    int y    = tile / 36;
    int rest = tile % 36;
    int x0   = (rest / 6) * 32;
    int z0   = (rest % 6) * 32;

#pragma unroll 4
    for (int zi = 0; zi < 32; zi++) {
        const float* rowp = &vol[((z0 + zi) * OUTN + y) * OUTN];
        smA[zi][lane] = __ldg(rowp + x0 + lane);
    }
    __syncwarp();

    int zq = (lane & 7) * 4;       // z-quad start
    int xg = lane >> 3;            // 0..3
#pragma unroll
    for (int it = 0; it < 8; it++) {
        int xi = xg + it * 4;
        float4 v = make_float4(smA[zq + 0][xi], smA[zq + 1][xi],
                               smA[zq + 2][xi], smA[zq + 3][xi]);
        *(float4*)&gVolT[((y * OUTN) + x0 + xi) * OUTN + z0 + zq] = v;
    }
    __syncwarp();
}

// ---------------- fused kernel: warps 0-6 rays, warps 7-15 build ----------------
__global__ void __launch_bounds__(512) ray_build_kernel(const float* __restrict__ RI,
                                                        const float* __restrict__ ray0,
                                                        const float* __restrict__ vol) {
    __shared__ float smA[BUILD_WARPS_PER_BLOCK][32][33];   // 38KB

    int wid  = threadIdx.x >> 5;
    int lane = threadIdx.x & 31;

    if (wid < RAY_WARPS_PER_BLOCK) {
        int warp_global = blockIdx.x * RAY_WARPS_PER_BLOCK + wid;
        if (warp_global < NRAY2 / 4)
            ray_body(RI, ray0, warp_global, lane);
    } else {
        int bw = blockIdx.x * BUILD_WARPS_PER_BLOCK + (wid - RAY_WARPS_PER_BLOCK);
        for (int tile = bw; tile < N_TILES; tile += N_BUILD_WARPS)
            build_tile(smA[wid - RAY_WARPS_PER_BLOCK], vol, tile, lane);
    }
}

// ---------------- phase 2: lane t handles cc = q*32+t -> contiguous z addresses ----------------
__device__ __forceinline__ float tap_slow(int x, int y, int z) {
    bool in = ((unsigned)x < 192u) && ((unsigned)y < 192u) && ((unsigned)z < 192u);
    int xc = min(max(x, 0), 191);
    int yc = min(max(y, 0), 191);
    int zc = min(max(z, 0), 191);
    float v = __ldg(&gVolT[((yc * OUTN) + xc) * OUTN + zc]);
    return in ? v : 0.0f;
}

__global__ void __launch_bounds__(256) sample_kernel(float* __restrict__ out) {
    int w = threadIdx.x >> 5;
    int t = threadIdx.x & 31;
    int row = blockIdx.x * 8 + w;
    int aa = row / OUTN, bb = row % OUTN;

    __shared__ float4 G4[8][64];

    const float scale = 63.0f / 191.0f;
    float pa = (float)aa * scale; int i0 = min((int)pa, 62); float wi = pa - (float)i0;
    float pb = (float)bb * scale; int j0 = min((int)pb, 62); float wj = pb - (float)j0;
    float u = 1.0f - wi, v = 1.0f - wj;
    int base = (i0 << 12) + (j0 << 6);

#pragma unroll
    for (int sb = 0; sb < 2; sb++) {
        int s = t + sb * 32;
        float4 a00 = gM4[base + s],      a10 = gM4[base + 4096 + s];
        float4 a01 = gM4[base + 64 + s], a11 = gM4[base + 4160 + s];
        float4 g;
        g.x = (a00.x * u + a10.x * wi) * v + (a01.x * u + a11.x * wi) * wj;
        g.y = (a00.y * u + a10.y * wi) * v + (a01.y * u + a11.y * wi) * wj;
        g.z = (a00.z * u + a10.z * wi) * v + (a01.z * u + a11.z * wi) * wj;
        g.w = 0.0f;
        G4[w][s] = g;
    }
    __syncwarp();

    int obase = row * OUTN;
#pragma unroll
    for (int q = 0; q < 6; q++) {
        int cc = q * 32 + t;
        float pc = (float)cc * scale; int s0 = min((int)pc, 62); float ws = pc - (float)s0;
        float4 g0 = G4[w][s0];
        float4 g1 = G4[w][s0 + 1];
        float gx = g0.x * (1.0f - ws) + g1.x * ws;
        float gy = g0.y * (1.0f - ws) + g1.y * ws;
        float gz = g0.z * (1.0f - ws) + g1.z * ws;

        float ix = (gx + 1.0f) * 0.5f * 191.0f;
        float iy = (gy + 1.0f) * 0.5f * 191.0f;
        float iz = (gz + 1.0f) * 0.5f * 191.0f;
        float xf = floorf(ix), yf = floorf(iy), zf = floorf(iz);
        float fx = ix - xf, fy = iy - yf, fz = iz - zf;
        int x0 = (int)xf, y0 = (int)yf, z0 = (int)zf;

        float v000, v001, v100, v101, v010, v011, v110, v111;
        bool lane_ok = ((unsigned)x0 <= 190u) && ((unsigned)y0 <= 190u) &&
                       ((unsigned)z0 <= 190u);
        if (__all_sync(0xffffffffu, lane_ok)) {
            const float* p = &gVolT[((y0 * OUTN) + x0) * OUTN + z0];
            v000 = __ldg(p);                  v001 = __ldg(p + 1);
            v100 = __ldg(p + OUTN);           v101 = __ldg(p + OUTN + 1);
            v010 = __ldg(p + OUTN*OUTN);      v011 = __ldg(p + OUTN*OUTN + 1);
            v110 = __ldg(p + OUTN*OUTN+OUTN); v111 = __ldg(p + OUTN*OUTN+OUTN + 1);
        } else {
            v000 = tap_slow(x0,     y0,     z0);
            v001 = tap_slow(x0,     y0,     z0 + 1);
            v100 = tap_slow(x0 + 1, y0,     z0);
            v101 = tap_slow(x0 + 1, y0,     z0 + 1);
            v010 = tap_slow(x0,     y0 + 1, z0);
            v011 = tap_slow(x0,     y0 + 1, z0 + 1);
            v110 = tap_slow(x0 + 1, y0 + 1, z0);
            v111 = tap_slow(x0 + 1, y0 + 1, z0 + 1);
        }

        float ux = 1.0f - fx, uy = 1.0f - fy;
        float r0 = uy * (ux * v000 + fx * v100) + fy * (ux * v010 + fx * v110);
        float r1 = uy * (ux * v001 + fx * v101) + fy * (ux * v011 + fx * v111);
        out[obase + cc] = r0 * (1.0f - fz) + r1 * fz;
    }
}

// ---------------- launch ----------------
extern "C" void kernel_launch(void* const* d_in, const int* in_sizes, int n_in,
                              void* d_out, int out_size) {
    const float* phantom = nullptr;
    const float* RI      = nullptr;
    const float* ray0    = nullptr;
    for (int i = 0; i < n_in; i++) {
        if      (in_sizes[i] == OUT3)                phantom = (const float*)d_in[i];
        else if (in_sizes[i] == KGRID*KGRID*KGRID*2) RI      = (const float*)d_in[i];
        else if (in_sizes[i] == NRAY2 * 5)           ray0    = (const float*)d_in[i];
    }
    float* out = (float*)d_out;

    ray_build_kernel<<<FUSED_BLOCKS, 512>>>(RI, ray0, phantom);
    sample_kernel<<<OUTN * OUTN / 8, 256>>>(out);
}